// round 1
// baseline (speedup 1.0000x reference)
#include <cuda_runtime.h>

// BoundaryFocalLoss: fused boundary-dilated focal BCE loss, scalar output.
// inputs: d_in[0]=inputs f32 [B*T], d_in[1]=targets i32 [B*T], d_in[2]=mask f32 [B*T]
// out: single f32 = sum(f_loss)/sum(mask)

#define T_LEN   200000
#define B_ROWS  128
#define T4      (T_LEN / 4)
#define NGROUPS (B_ROWS * T4)
#define NBLK    2048
#define NTHR    256

#define ALPHA          0.25f
#define BOUNDARY_W     5.0f
#define LABEL_SMOOTH   0.05f

__device__ double g_partial_f[NBLK];
__device__ double g_partial_m[NBLK];

__device__ __forceinline__ float elem_loss(float x, int t, float m, bool bd) {
    float pos      = (t != 0) ? 1.0f : 0.0f;
    float smoothed = fmaf(pos, 1.0f - LABEL_SMOOTH, LABEL_SMOOTH * 0.5f);

    float w = bd ? BOUNDARY_W : 1.0f;

    // adaptive = 1 - |sigmoid(x) - 0.5|  (symmetric in sign of x)
    float ea = __expf(-fabsf(x));          // in (0, 1]
    float inv = __frcp_rn(1.0f + ea);      // = p for x>=0, >= 0.5
    float adaptive = 1.5f - inv;
    w *= adaptive;

    float bce = fmaxf(x, 0.0f) - x * smoothed + __logf(1.0f + ea);
    float pt  = __expf(-bce);
    float alpha_w = (t != 0) ? ALPHA : (1.0f - ALPHA);
    float om = 1.0f - pt;
    return alpha_w * om * om * bce * w * m;
}

__global__ void __launch_bounds__(NTHR)
bfl_main(const float* __restrict__ in, const int* __restrict__ tgt,
         const float* __restrict__ mask) {
    float acc_f_local;
    double acc_f = 0.0, acc_m = 0.0;

    for (int g = blockIdx.x * NTHR + threadIdx.x; g < NGROUPS; g += NBLK * NTHR) {
        int b    = g / T4;
        int c0   = (g - b * T4) * 4;
        int base = b * T_LEN;

        const float4 xv = __ldg((const float4*)(in   + base + c0));
        const float4 mv = __ldg((const float4*)(mask + base + c0));
        const int4   tv = __ldg((const int4*)  (tgt  + base + c0));

        // neighbor targets, clamped to row bounds (clamp => duplicated value => no transition)
        int a0 = __ldg(tgt + base + max(c0 - 4, 0));
        int a1 = __ldg(tgt + base + max(c0 - 3, 0));
        int a2 = __ldg(tgt + base + max(c0 - 2, 0));
        int a3 = __ldg(tgt + base + max(c0 - 1, 0));
        int p1 = __ldg(tgt + base + min(c0 + 4, T_LEN - 1));
        int p2 = __ldg(tgt + base + min(c0 + 5, T_LEN - 1));
        int p3 = __ldg(tgt + base + min(c0 + 6, T_LEN - 1));

        int arr[11] = {a0, a1, a2, a3, tv.x, tv.y, tv.z, tv.w, p1, p2, p3};
        unsigned dm = 0;
        #pragma unroll
        for (int j = 1; j < 11; j++)
            dm |= ((unsigned)(arr[j] != arr[j - 1])) << j;

        // boundary for element k (col c0+k): any transition in cols [c0+k-3, c0+k+3]
        // transition at col c0-4+j corresponds to bit j => bits (k+1)..(k+7)
        bool b0 = (dm >> 1) & 0x7F;
        bool b1 = (dm >> 2) & 0x7F;
        bool b2 = (dm >> 3) & 0x7F;
        bool b3 = (dm >> 4) & 0x7F;

        acc_f_local  = elem_loss(xv.x, tv.x, mv.x, b0);
        acc_f_local += elem_loss(xv.y, tv.y, mv.y, b1);
        acc_f_local += elem_loss(xv.z, tv.z, mv.z, b2);
        acc_f_local += elem_loss(xv.w, tv.w, mv.w, b3);

        acc_f += (double)acc_f_local;
        acc_m += (double)(mv.x + mv.y + mv.z + mv.w);
    }

    __shared__ double sf[NTHR];
    __shared__ double sm[NTHR];
    int tid = threadIdx.x;
    sf[tid] = acc_f;
    sm[tid] = acc_m;
    __syncthreads();
    #pragma unroll
    for (int s = NTHR / 2; s > 0; s >>= 1) {
        if (tid < s) { sf[tid] += sf[tid + s]; sm[tid] += sm[tid + s]; }
        __syncthreads();
    }
    if (tid == 0) {
        g_partial_f[blockIdx.x] = sf[0];
        g_partial_m[blockIdx.x] = sm[0];
    }
}

__global__ void __launch_bounds__(NTHR)
bfl_finalize(float* __restrict__ out) {
    __shared__ double sf[NTHR];
    __shared__ double sm[NTHR];
    int tid = threadIdx.x;
    double a = 0.0, b = 0.0;
    for (int i = tid; i < NBLK; i += NTHR) {
        a += g_partial_f[i];
        b += g_partial_m[i];
    }
    sf[tid] = a;
    sm[tid] = b;
    __syncthreads();
    #pragma unroll
    for (int s = NTHR / 2; s > 0; s >>= 1) {
        if (tid < s) { sf[tid] += sf[tid + s]; sm[tid] += sm[tid + s]; }
        __syncthreads();
    }
    if (tid == 0)
        out[0] = (sm[0] > 0.0) ? (float)(sf[0] / sm[0]) : 0.0f;
}

extern "C" void kernel_launch(void* const* d_in, const int* in_sizes, int n_in,
                              void* d_out, int out_size) {
    const float* in   = (const float*)d_in[0];
    const int*   tgt  = (const int*)d_in[1];
    const float* mask = (const float*)d_in[2];
    float* out = (float*)d_out;
    (void)in_sizes; (void)n_in; (void)out_size;

    bfl_main<<<NBLK, NTHR>>>(in, tgt, mask);
    bfl_finalize<<<1, NTHR>>>(out);
}